// round 2
// baseline (speedup 1.0000x reference)
#include <cuda_runtime.h>

// NTM forward: B=2048, T=64, I=9, N=128, V=20, S=3, C=100, O=8
#define TT 64
#define II 9
#define NN 128
#define VV 20
#define CC 100
#define OO 8
#define MPITCH 21   // padded row stride for M in smem (odd -> conflict-free)
#define EPSF 1e-8f

__device__ __forceinline__ float sigmoidf_(float x) {
    return 1.0f / (1.0f + __expf(-x));
}
__device__ __forceinline__ float softplusf_(float x) {
    return fmaxf(x, 0.0f) + log1pf(__expf(-fabsf(x)));
}
__device__ __forceinline__ float ex2_(float x) {   // fast 2^x (MUFU.EX2)
    float r;
    asm("ex2.approx.ftz.f32 %0, %1;" : "=f"(r) : "f"(x));
    return r;
}

// Block-wide sum over 128 threads. Includes trailing sync so `red` can be reused.
__device__ __forceinline__ float blkSum128(float v, float* red, int lane, int wid) {
    #pragma unroll
    for (int o = 16; o; o >>= 1) v += __shfl_xor_sync(0xffffffffu, v, o);
    if (lane == 0) red[wid] = v;
    __syncthreads();
    float s = red[0] + red[1] + red[2] + red[3];
    __syncthreads();
    return s;
}
__device__ __forceinline__ float blkMax128(float v, float* red, int lane, int wid) {
    #pragma unroll
    for (int o = 16; o; o >>= 1) v = fmaxf(v, __shfl_xor_sync(0xffffffffu, v, o));
    if (lane == 0) red[wid] = v;
    __syncthreads();
    float s = fmaxf(fmaxf(red[0], red[1]), fmaxf(red[2], red[3]));
    __syncthreads();
    return s;
}

// Addressing for one head. dot/mnorm/wp already valid (synced). Writes wout[tid];
// caller must __syncthreads() before consuming wout.
__device__ __forceinline__ void address_head(
    int tid, int lane, int wid,
    const float* __restrict__ dot, float kn, float beta, float g,
    float s0, float s1, float s2, float gamma,
    const float* __restrict__ mnorm, const float* __restrict__ wp,
    float* __restrict__ wout, float* __restrict__ wg, float* red)
{
    float sim = __fdividef(dot[tid], fmaf(kn, mnorm[tid], EPSF));
    float z = beta * sim;
    float mx = blkMax128(z, red, lane, wid);
    float e = __expf(z - mx);
    float se = blkSum128(e, red, lane, wid);
    float wc = __fdividef(e, se);
    // w_g = g*wc + (1-g)*wp
    wg[tid] = fmaf(g, wc - wp[tid], wp[tid]);
    __syncthreads();
    // circular conv: w_s[n] = s0*wg[n+1] + s1*wg[n] + s2*wg[n-1]  (mod 128)
    float ws = s0 * wg[(tid + 1) & (NN - 1)] + s1 * wg[tid] + s2 * wg[(tid + NN - 1) & (NN - 1)];
    // sharpening: ws^gamma
    float wpow = (ws > 0.0f) ? ex2_(gamma * __log2f(ws)) : 0.0f;
    float sp = blkSum128(wpow, red, lane, wid);
    wout[tid] = __fdividef(wpow, sp + EPSF);
}

__global__ __launch_bounds__(128) void ntm_kernel(
    const float* __restrict__ x,
    const float* __restrict__ Wc, const float* __restrict__ bc,
    const float* __restrict__ Wr, const float* __restrict__ br,
    const float* __restrict__ Ww, const float* __restrict__ bw,
    const float* __restrict__ Wf, const float* __restrict__ bf,
    const float* __restrict__ r_bias, const float* __restrict__ M_bias,
    float* __restrict__ out, int Btot)
{
    __shared__ float Ms[NN * MPITCH];     // memory, padded rows
    __shared__ float cat[32];             // [x_t(9), r(20)]
    __shared__ float h[CC];
    __shared__ float p[92];               // read(26) + write(66) pre-activations
    __shared__ float kr[VV], kw[VV], ev[VV], av[VV];
    __shared__ float wprev[NN], wr[NN], wg[NN];
    __shared__ float dotr[NN], dotw[NN], mnorm[NN];
    __shared__ float part[80];
    __shared__ float red[4];
    __shared__ float scal[12];            // [br,gr,gammar,sr0..2, bw,gw,gammaw,sw0..2]
    __shared__ float knorm[2];

    const int tid = threadIdx.x;
    const int lane = tid & 31, wid = tid >> 5;

    for (int b = blockIdx.x; b < Btot; b += gridDim.x) {
        // ---- init state for this batch element ----
        for (int idx = tid; idx < NN * VV; idx += 128)
            Ms[(idx / VV) * MPITCH + (idx % VV)] = M_bias[idx];
        if (tid < VV) cat[II + tid] = r_bias[tid];
        wprev[tid] = 0.0f;
        __syncthreads();

        const float* xb = x + (size_t)b * TT * II;
        float* ob = out + (size_t)b * TT * OO;

        for (int t = 0; t < TT; ++t) {
            // ---- load x_t ----
            if (tid < II) cat[tid] = xb[t * II + tid];
            __syncthreads();

            // ---- controller: h = tanh(cat @ Wc + bc) ----
            if (tid < CC) {
                float acc = bc[tid];
                #pragma unroll
                for (int i = 0; i < II + VV; ++i)
                    acc = fmaf(cat[i], Wc[i * CC + tid], acc);
                h[tid] = tanhf(acc);
            }
            __syncthreads();

            // ---- head pre-activations: p[0:26]=h@Wr+br, p[26:92]=h@Ww+bw ----
            if (tid < 92) {
                float acc;
                if (tid < 26) {
                    acc = br[tid];
                    #pragma unroll 4
                    for (int c = 0; c < CC; ++c) acc = fmaf(h[c], Wr[c * 26 + tid], acc);
                } else {
                    const int o = tid - 26;
                    acc = bw[o];
                    #pragma unroll 4
                    for (int c = 0; c < CC; ++c) acc = fmaf(h[c], Ww[c * 66 + o], acc);
                }
                p[tid] = acc;
            }
            __syncthreads();

            // ---- head nonlinearities ----
            if (tid < VV)                    kr[tid]       = tanhf(p[tid]);
            if (tid >= 32 && tid < 32 + VV)  kw[tid - 32]  = tanhf(p[26 + (tid - 32)]);
            if (tid >= 64 && tid < 64 + VV)  ev[tid - 64]  = sigmoidf_(p[52 + (tid - 64)]);
            if (tid >= 96 && tid < 96 + VV)  av[tid - 96]  = tanhf(p[72 + (tid - 96)]);
            if (tid == 20) scal[0] = softplusf_(p[20]);            // beta_r
            if (tid == 21) scal[1] = sigmoidf_(p[21]);             // g_r
            if (tid == 22) scal[2] = 1.0f + softplusf_(p[25]);     // gamma_r
            if (tid == 23) {                                       // s_r softmax(3)
                float a0 = p[22], a1 = p[23], a2 = p[24];
                float m = fmaxf(a0, fmaxf(a1, a2));
                float e0 = __expf(a0 - m), e1 = __expf(a1 - m), e2 = __expf(a2 - m);
                float s = e0 + e1 + e2;
                scal[3] = e0 / s; scal[4] = e1 / s; scal[5] = e2 / s;
            }
            if (tid == 52) scal[6] = softplusf_(p[46]);            // beta_w
            if (tid == 53) scal[7] = sigmoidf_(p[47]);             // g_w
            if (tid == 54) scal[8] = 1.0f + softplusf_(p[51]);     // gamma_w
            if (tid == 55) {                                       // s_w softmax(3)
                float a0 = p[48], a1 = p[49], a2 = p[50];
                float m = fmaxf(a0, fmaxf(a1, a2));
                float e0 = __expf(a0 - m), e1 = __expf(a1 - m), e2 = __expf(a2 - m);
                float s = e0 + e1 + e2;
                scal[9] = e0 / s; scal[10] = e1 / s; scal[11] = e2 / s;
            }
            __syncthreads();

            // ---- fused pass over M: dot_r, dot_w, row norms (+ k norms) ----
            {
                float dr = 0.0f, dw = 0.0f, ss = 0.0f;
                const float* Mrow = &Ms[tid * MPITCH];
                #pragma unroll
                for (int v = 0; v < VV; ++v) {
                    float m = Mrow[v];
                    dr = fmaf(m, kr[v], dr);
                    dw = fmaf(m, kw[v], dw);
                    ss = fmaf(m, m, ss);
                }
                dotr[tid] = dr; dotw[tid] = dw; mnorm[tid] = sqrtf(ss);
                if (tid == 24) {
                    float s2 = 0.0f;
                    #pragma unroll
                    for (int v = 0; v < VV; ++v) s2 = fmaf(kr[v], kr[v], s2);
                    knorm[0] = sqrtf(s2);
                }
                if (tid == 56) {
                    float s2 = 0.0f;
                    #pragma unroll
                    for (int v = 0; v < VV; ++v) s2 = fmaf(kw[v], kw[v], s2);
                    knorm[1] = sqrtf(s2);
                }
            }
            __syncthreads();

            // ---- read head addressing -> wr ----
            address_head(tid, lane, wid, dotr, knorm[0],
                         scal[0], scal[1], scal[3], scal[4], scal[5], scal[2],
                         mnorm, wprev, wr, wg, red);
            __syncthreads();

            // ---- r = wr @ M  -> cat[9:29] ----
            if (tid < 80) {
                const int v = tid % 20, q = tid / 20;
                const int base = q * 32;
                float acc = 0.0f;
                #pragma unroll 8
                for (int j = 0; j < 32; ++j)
                    acc = fmaf(wr[base + j], Ms[(base + j) * MPITCH + v], acc);
                part[tid] = acc;
            }
            __syncthreads();
            if (tid < VV)
                cat[II + tid] = part[tid] + part[20 + tid] + part[40 + tid] + part[60 + tid];
            __syncthreads();

            // ---- write head addressing (w_prev = wr) -> wprev (becomes next w_p) ----
            address_head(tid, lane, wid, dotw, knorm[1],
                         scal[6], scal[7], scal[9], scal[10], scal[11], scal[8],
                         mnorm, wr, wprev, wg, red);
            __syncthreads();

            // ---- memory update: M = M + ww*(a - e*M) ----
            {
                const float wwn = wprev[tid];
                float* Mrow = &Ms[tid * MPITCH];
                #pragma unroll
                for (int v = 0; v < VV; ++v) {
                    float m = Mrow[v];
                    Mrow[v] = fmaf(wwn, av[v] - ev[v] * m, m);
                }
            }

            // ---- output: sigmoid([h, r] @ Wf + bf) ----
            if (tid < 64) {
                const int o = tid & 7, seg = tid >> 3;   // 8 segs of 15
                float acc = 0.0f;
                #pragma unroll
                for (int j = seg * 15; j < seg * 15 + 15; ++j) {
                    float v = (j < CC) ? h[j] : cat[II + (j - CC)];
                    acc = fmaf(v, Wf[j * 8 + o], acc);
                }
                part[tid] = acc;
            }
            __syncthreads();
            if (tid < OO) {
                float s = bf[tid];
                #pragma unroll
                for (int q = 0; q < 8; ++q) s += part[q * 8 + tid];
                ob[t * OO + tid] = sigmoidf_(s);
            }
            __syncthreads();
        }
        __syncthreads();
    }
}

extern "C" void kernel_launch(void* const* d_in, const int* in_sizes, int n_in,
                              void* d_out, int out_size) {
    const float* x      = (const float*)d_in[0];
    const float* Wc     = (const float*)d_in[1];
    const float* bc     = (const float*)d_in[2];
    const float* Wr     = (const float*)d_in[3];
    const float* br     = (const float*)d_in[4];
    const float* Ww     = (const float*)d_in[5];
    const float* bw     = (const float*)d_in[6];
    const float* Wf     = (const float*)d_in[7];
    const float* bf     = (const float*)d_in[8];
    const float* r_bias = (const float*)d_in[9];
    const float* M_bias = (const float*)d_in[10];
    float* out = (float*)d_out;

    const int Btot = in_sizes[0] / (TT * II);
    int grid = (Btot + 1) / 2;              // each CTA handles 2 batch elems, balanced
    if (grid < 1) grid = 1;
    ntm_kernel<<<grid, 128>>>(x, Wc, bc, Wr, br, Ww, bw, Wf, bf, r_bias, M_bias, out, Btot);
}

// round 4
// speedup vs baseline: 1.0751x; 1.0751x over previous
#include <cuda_runtime.h>

// NTM forward: B=2048, T=64, I=9, N=128, V=20, S=3, C=100, O=8
#define TT 64
#define II 9
#define NN 128
#define VV 20
#define CC 100
#define OO 8
#define MPITCH 21   // padded row stride for M in smem (odd -> conflict-free)
#define EPSF 1e-8f

__device__ __forceinline__ float sigmoidf_(float x) {
    return 1.0f / (1.0f + __expf(-x));
}
__device__ __forceinline__ float softplusf_(float x) {
    return fmaxf(x, 0.0f) + log1pf(__expf(-fabsf(x)));
}
__device__ __forceinline__ float ex2_(float x) {   // fast 2^x (MUFU.EX2)
    float r;
    asm("ex2.approx.ftz.f32 %0, %1;" : "=f"(r) : "f"(x));
    return r;
}

__global__ __launch_bounds__(128, 6) void ntm_kernel(
    const float* __restrict__ x,
    const float* __restrict__ Wc, const float* __restrict__ bc,
    const float* __restrict__ Wr, const float* __restrict__ br,
    const float* __restrict__ Ww, const float* __restrict__ bw,
    const float* __restrict__ Wf, const float* __restrict__ bf,
    const float* __restrict__ r_bias, const float* __restrict__ M_bias,
    float* __restrict__ out, int Btot)
{
    __shared__ float Ms[NN * MPITCH];     // memory, padded rows
    __shared__ float cat[32];             // [x_t(9), r(20)]
    __shared__ float h[CC];
    __shared__ float kr[VV], kw[VV], ev[VV], av[VV];
    __shared__ float wprev[NN], wr[NN], wg[NN];
    __shared__ float dotr[NN], dotw[NN], mnorm[NN];
    __shared__ float part[80];
    __shared__ float redA[4], redB[4];
    __shared__ float scal[12];  // [beta_r,g_r,gamma_r,s_r(3), beta_w,g_w,gamma_w,s_w(3)]
    __shared__ float praw[6];   // raw shift logits (read:0..2, write:3..5)
    __shared__ float knorm[2];

    const int tid = threadIdx.x;
    const int lane = tid & 31, wid = tid >> 5;

    for (int b = blockIdx.x; b < Btot; b += gridDim.x) {
        // ---- init state for this batch element ----
        for (int idx = tid; idx < NN * VV; idx += 128)
            Ms[(idx / VV) * MPITCH + (idx % VV)] = M_bias[idx];
        if (tid < VV) cat[II + tid] = r_bias[tid];
        wprev[tid] = 0.0f;

        const float* xb = x + (size_t)b * TT * II;
        float* ob = out + (size_t)b * TT * OO;

        if (tid < II) cat[tid] = xb[tid];   // x_0
        __syncthreads();

        for (int t = 0; t < TT; ++t) {
            // ---- B: controller h = tanh(cat @ Wc + bc) ----
            if (tid < CC) {
                float acc = bc[tid];
                #pragma unroll
                for (int i = 0; i < II + VV; ++i)
                    acc = fmaf(cat[i], Wc[i * CC + tid], acc);
                h[tid] = tanhf(acc);
            }
            __syncthreads();

            // ---- C: head pre-activations, fused nonlinearity (per-thread) ----
            if (tid < 92) {
                float acc;
                if (tid < 26) {
                    acc = br[tid];
                    #pragma unroll 4
                    for (int c = 0; c < CC; ++c) acc = fmaf(h[c], Wr[c * 26 + tid], acc);
                } else {
                    const int o = tid - 26;
                    acc = bw[o];
                    #pragma unroll 4
                    for (int c = 0; c < CC; ++c) acc = fmaf(h[c], Ww[c * 66 + o], acc);
                }
                // per-thread activation dispatch
                if (tid < 20)       kr[tid] = tanhf(acc);
                else if (tid == 20) scal[0] = softplusf_(acc);          // beta_r
                else if (tid == 21) scal[1] = sigmoidf_(acc);           // g_r
                else if (tid < 25)  praw[tid - 22] = acc;               // s_r logits
                else if (tid == 25) scal[2] = 1.0f + softplusf_(acc);   // gamma_r
                else if (tid < 46)  kw[tid - 26] = tanhf(acc);
                else if (tid == 46) scal[6] = softplusf_(acc);          // beta_w
                else if (tid == 47) scal[7] = sigmoidf_(acc);           // g_w
                else if (tid < 51)  praw[3 + tid - 48] = acc;           // s_w logits
                else if (tid == 51) scal[8] = 1.0f + softplusf_(acc);   // gamma_w
                else if (tid < 72)  ev[tid - 52] = sigmoidf_(acc);      // erase
                else                av[tid - 72] = tanhf(acc);          // add
            }
            __syncthreads();

            // ---- D: fused pass over M (dot_r, dot_w, row norm) + side jobs ----
            {
                float dr = 0.0f, dw = 0.0f, ss = 0.0f;
                const float* Mrow = &Ms[tid * MPITCH];
                #pragma unroll
                for (int v = 0; v < VV; ++v) {
                    float m = Mrow[v];
                    dr = fmaf(m, kr[v], dr);
                    dw = fmaf(m, kw[v], dw);
                    ss = fmaf(m, m, ss);
                }
                dotr[tid] = dr; dotw[tid] = dw; mnorm[tid] = sqrtf(ss);
            }
            if (tid == 96) {                                  // s_r softmax(3)
                float a0 = praw[0], a1 = praw[1], a2 = praw[2];
                float m = fmaxf(a0, fmaxf(a1, a2));
                float e0 = __expf(a0 - m), e1 = __expf(a1 - m), e2 = __expf(a2 - m);
                float s = e0 + e1 + e2;
                scal[3] = e0 / s; scal[4] = e1 / s; scal[5] = e2 / s;
            } else if (tid == 97) {                           // |kr|
                float s2 = 0.0f;
                #pragma unroll
                for (int v = 0; v < VV; ++v) s2 = fmaf(kr[v], kr[v], s2);
                knorm[0] = sqrtf(s2);
            } else if (tid == 98) {                           // s_w softmax(3)
                float a0 = praw[3], a1 = praw[4], a2 = praw[5];
                float m = fmaxf(a0, fmaxf(a1, a2));
                float e0 = __expf(a0 - m), e1 = __expf(a1 - m), e2 = __expf(a2 - m);
                float s = e0 + e1 + e2;
                scal[9] = e0 / s; scal[10] = e1 / s; scal[11] = e2 / s;
            } else if (tid == 99) {                           // |kw|
                float s2 = 0.0f;
                #pragma unroll
                for (int v = 0; v < VV; ++v) s2 = fmaf(kw[v], kw[v], s2);
                knorm[1] = sqrtf(s2);
            }
            __syncthreads();

            // ---- E: dual-head content softmax (shared reduction rounds) ----
            const float beta_r = scal[0], g_r = scal[1], gamma_r = scal[2];
            const float s0r = scal[3], s1r = scal[4], s2r = scal[5];
            const float beta_w = scal[6], g_w = scal[7], gamma_w = scal[8];
            const float s0w = scal[9], s1w = scal[10], s2w = scal[11];
            const float mn = mnorm[tid];
            float zr = beta_r * __fdividef(dotr[tid], fmaf(knorm[0], mn, EPSF));
            float zw = beta_w * __fdividef(dotw[tid], fmaf(knorm[1], mn, EPSF));
            float mr = zr, mw = zw;
            #pragma unroll
            for (int o = 16; o; o >>= 1) {
                mr = fmaxf(mr, __shfl_xor_sync(0xffffffffu, mr, o));
                mw = fmaxf(mw, __shfl_xor_sync(0xffffffffu, mw, o));
            }
            if (lane == 0) { redA[wid] = mr; redB[wid] = mw; }
            __syncthreads();
            mr = fmaxf(fmaxf(redA[0], redA[1]), fmaxf(redA[2], redA[3]));
            mw = fmaxf(fmaxf(redB[0], redB[1]), fmaxf(redB[2], redB[3]));
            float er = __expf(zr - mr), ew = __expf(zw - mw);
            float sr = er, sw = ew;
            #pragma unroll
            for (int o = 16; o; o >>= 1) {
                sr += __shfl_xor_sync(0xffffffffu, sr, o);
                sw += __shfl_xor_sync(0xffffffffu, sw, o);
            }
            __syncthreads();                 // protect redA/redB reuse
            if (lane == 0) { redA[wid] = sr; redB[wid] = sw; }
            __syncthreads();
            const float wcr = __fdividef(er, redA[0] + redA[1] + redA[2] + redA[3]);
            const float wcw = __fdividef(ew, redB[0] + redB[1] + redB[2] + redB[3]);

            // ---- F: read-head interpolation, shift, sharpen ----
            wg[tid] = fmaf(g_r, wcr - wprev[tid], wprev[tid]);
            __syncthreads();
            {
                float ws = s0r * wg[(tid + 1) & (NN - 1)] + s1r * wg[tid]
                         + s2r * wg[(tid + NN - 1) & (NN - 1)];
                float wpow = (ws > 0.0f) ? ex2_(gamma_r * __log2f(ws)) : 0.0f;
                float sp = wpow;
                #pragma unroll
                for (int o = 16; o; o >>= 1) sp += __shfl_xor_sync(0xffffffffu, sp, o);
                if (lane == 0) redA[wid] = sp;
                __syncthreads();
                sp = redA[0] + redA[1] + redA[2] + redA[3];
                wr[tid] = __fdividef(wpow, sp + EPSF);
            }
            __syncthreads();

            // ---- G: r = wr @ M  (80 thr)  ||  write-head interpolation (all) ----
            wg[tid] = fmaf(g_w, wcw - wr[tid], wr[tid]);
            if (tid < 80) {
                const int v = tid % 20, q = tid / 20;
                const int base = q * 32;
                float acc = 0.0f;
                #pragma unroll 8
                for (int j = 0; j < 32; ++j)
                    acc = fmaf(wr[base + j], Ms[(base + j) * MPITCH + v], acc);
                part[tid] = acc;
            }
            __syncthreads();

            // ---- H: write-head shift+sharpen  ||  r combine ----
            float wpoww;
            {
                float ws = s0w * wg[(tid + 1) & (NN - 1)] + s1w * wg[tid]
                         + s2w * wg[(tid + NN - 1) & (NN - 1)];
                wpoww = (ws > 0.0f) ? ex2_(gamma_w * __log2f(ws)) : 0.0f;
                float sp = wpoww;
                #pragma unroll
                for (int o = 16; o; o >>= 1) sp += __shfl_xor_sync(0xffffffffu, sp, o);
                if (lane == 0) redB[wid] = sp;
            }
            if (tid < VV)
                cat[II + tid] = part[tid] + part[20 + tid] + part[40 + tid] + part[60 + tid];
            __syncthreads();

            // ---- I: finalize ww, update M row  ||  output partials ----
            {
                float sp = redB[0] + redB[1] + redB[2] + redB[3];
                float ww = __fdividef(wpoww, sp + EPSF);
                wprev[tid] = ww;
                float* Mrow = &Ms[tid * MPITCH];
                #pragma unroll
                for (int v = 0; v < VV; ++v) {
                    float m = Mrow[v];
                    Mrow[v] = fmaf(ww, av[v] - ev[v] * m, m);
                }
            }
            if (tid < 64) {
                const int o = tid & 7, seg = tid >> 3;   // 8 segs of 15
                float acc = 0.0f;
                #pragma unroll
                for (int j = seg * 15; j < seg * 15 + 15; ++j) {
                    float v = (j < CC) ? h[j] : cat[II + (j - CC)];
                    acc = fmaf(v, Wf[j * 8 + o], acc);
                }
                part[tid] = acc;
            }
            __syncthreads();

            // ---- J: output store  ||  prefetch x_{t+1} ----
            if (tid < OO) {
                float s = bf[tid];
                #pragma unroll
                for (int q = 0; q < 8; ++q) s += part[q * 8 + tid];
                ob[t * OO + tid] = sigmoidf_(s);
            }
            if (tid >= 96 && tid < 96 + II && t + 1 < TT)
                cat[tid - 96] = xb[(t + 1) * II + (tid - 96)];
            __syncthreads();
        }
        __syncthreads();
    }
}

extern "C" void kernel_launch(void* const* d_in, const int* in_sizes, int n_in,
                              void* d_out, int out_size) {
    const float* x      = (const float*)d_in[0];
    const float* Wc     = (const float*)d_in[1];
    const float* bc     = (const float*)d_in[2];
    const float* Wr     = (const float*)d_in[3];
    const float* br     = (const float*)d_in[4];
    const float* Ww     = (const float*)d_in[5];
    const float* bw     = (const float*)d_in[6];
    const float* Wf     = (const float*)d_in[7];
    const float* bf     = (const float*)d_in[8];
    const float* r_bias = (const float*)d_in[9];
    const float* M_bias = (const float*)d_in[10];
    float* out = (float*)d_out;

    const int Btot = in_sizes[0] / (TT * II);
    int grid = (Btot + 1) / 2;              // 2 batch elems per CTA, sequential
    if (grid < 1) grid = 1;
    ntm_kernel<<<grid, 128>>>(x, Wc, bc, Wr, br, Ww, bw, Wf, bf, r_bias, M_bias, out, Btot);
}

// round 6
// speedup vs baseline: 1.2828x; 1.1932x over previous
#include <cuda_runtime.h>

// NTM forward: B=2048, T=64, I=9, N=128, V=20, S=3, C=100, O=8
#define TT 64
#define II 9
#define NN 128
#define VV 20
#define CC 100
#define OO 8
#define MPITCH 21
#define EPSF 1e-8f

// smem weight layout (floats)
#define WC_OFF 0            // 29*100 = 2900
#define WR_OFF 2900         // 100*26 = 2600
#define WW_OFF 5500         // 100*66 = 6600
#define WF_OFF 12100        // 120*8  = 960
#define BC_OFF 13060        // 100
#define BR_OFF 13160        // 26
#define BW_OFF 13186        // 66
#define BF_OFF 13252        // 8
#define GS_OFF 13260

struct GroupState {
    float Ms[NN * MPITCH];                 // 2688
    float cat[32];
    float h[CC];
    float kr[VV], kw[VV], ev[VV], av[VV];
    float wprev[NN], wr[NN], wg[NN];
    float dotr[NN], dotw[NN], mnorm[NN];
    float part[80];
    float redA[4], redB[4];
    float scal[12];
    float praw[6];
    float knorm[2];
};  // 3776 floats

#define DYN_SMEM_BYTES ((GS_OFF + 2 * (int)(sizeof(GroupState) / 4)) * 4)

__device__ __forceinline__ float sigmoidf_(float x) {
    return 1.0f / (1.0f + __expf(-x));
}
__device__ __forceinline__ float softplusf_(float x) {
    return fmaxf(x, 0.0f) + log1pf(__expf(-fabsf(x)));
}
__device__ __forceinline__ float ex2_(float x) {
    float r;
    asm("ex2.approx.ftz.f32 %0, %1;" : "=f"(r) : "f"(x));
    return r;
}
__device__ __forceinline__ void gbar(int g) {   // 128-thread group barrier
    asm volatile("bar.sync %0, 128;" :: "r"(g + 1) : "memory");
}

__global__ __launch_bounds__(256, 2) void ntm_kernel(
    const float* __restrict__ x,
    const float* __restrict__ Wc, const float* __restrict__ bc,
    const float* __restrict__ Wr, const float* __restrict__ br,
    const float* __restrict__ Ww, const float* __restrict__ bw,
    const float* __restrict__ Wf, const float* __restrict__ bf,
    const float* __restrict__ r_bias, const float* __restrict__ M_bias,
    float* __restrict__ out, int Btot)
{
    extern __shared__ float sm[];

    const int tid = threadIdx.x;
    // ---- one-time weight+bias load into smem (all 256 threads) ----
    for (int i = tid; i < 2900; i += 256) sm[WC_OFF + i] = Wc[i];
    for (int i = tid; i < 2600; i += 256) sm[WR_OFF + i] = Wr[i];
    for (int i = tid; i < 6600; i += 256) sm[WW_OFF + i] = Ww[i];
    for (int i = tid; i < 960;  i += 256) sm[WF_OFF + i] = Wf[i];
    for (int i = tid; i < 100;  i += 256) sm[BC_OFF + i] = bc[i];
    for (int i = tid; i < 26;   i += 256) sm[BR_OFF + i] = br[i];
    for (int i = tid; i < 66;   i += 256) sm[BW_OFF + i] = bw[i];
    for (int i = tid; i < 8;    i += 256) sm[BF_OFF + i] = bf[i];
    __syncthreads();

    const int group = tid >> 7;          // 0 or 1
    const int gtid = tid & 127;
    const int lane = gtid & 31, gwid = gtid >> 5;
    GroupState* gs = reinterpret_cast<GroupState*>(sm + GS_OFF) + group;

    const float* Wcs = sm + WC_OFF; const float* Wrs = sm + WR_OFF;
    const float* Wws = sm + WW_OFF; const float* Wfs = sm + WF_OFF;
    const float* bcs = sm + BC_OFF; const float* brs = sm + BR_OFF;
    const float* bws = sm + BW_OFF; const float* bfs = sm + BF_OFF;

    for (int b = blockIdx.x * 2 + group; b < Btot; b += gridDim.x * 2) {
        // ---- init state ----
        for (int idx = gtid; idx < NN * VV; idx += 128)
            gs->Ms[(idx / VV) * MPITCH + (idx % VV)] = M_bias[idx];
        if (gtid < VV) gs->cat[II + gtid] = r_bias[gtid];
        gs->wprev[gtid] = 0.0f;

        const float* xb = x + (size_t)b * TT * II;
        float* ob = out + (size_t)b * TT * OO;
        if (gtid < II) gs->cat[gtid] = xb[gtid];
        gbar(group);

        for (int t = 0; t < TT; ++t) {
            // ---- B: controller h = tanh(cat @ Wc + bc) ----
            if (gtid < CC) {
                float acc = bcs[gtid];
                #pragma unroll
                for (int i = 0; i < II + VV; ++i)
                    acc = fmaf(gs->cat[i], Wcs[i * CC + gtid], acc);
                gs->h[gtid] = tanhf(acc);
            }
            gbar(group);

            // ---- C: head pre-activations + fused nonlinearity ----
            if (gtid < 92) {
                float acc;
                if (gtid < 26) {
                    acc = brs[gtid];
                    #pragma unroll 4
                    for (int c = 0; c < CC; ++c) acc = fmaf(gs->h[c], Wrs[c * 26 + gtid], acc);
                } else {
                    const int o = gtid - 26;
                    acc = bws[o];
                    #pragma unroll 4
                    for (int c = 0; c < CC; ++c) acc = fmaf(gs->h[c], Wws[c * 66 + o], acc);
                }
                if (gtid < 20)       gs->kr[gtid] = tanhf(acc);
                else if (gtid == 20) gs->scal[0] = softplusf_(acc);
                else if (gtid == 21) gs->scal[1] = sigmoidf_(acc);
                else if (gtid < 25)  gs->praw[gtid - 22] = acc;
                else if (gtid == 25) gs->scal[2] = 1.0f + softplusf_(acc);
                else if (gtid < 46)  gs->kw[gtid - 26] = tanhf(acc);
                else if (gtid == 46) gs->scal[6] = softplusf_(acc);
                else if (gtid == 47) gs->scal[7] = sigmoidf_(acc);
                else if (gtid < 51)  gs->praw[3 + gtid - 48] = acc;
                else if (gtid == 51) gs->scal[8] = 1.0f + softplusf_(acc);
                else if (gtid < 72)  gs->ev[gtid - 52] = sigmoidf_(acc);
                else                 gs->av[gtid - 72] = tanhf(acc);
            }
            gbar(group);

            // ---- D: fused pass over M + side jobs ----
            {
                float dr = 0.0f, dw = 0.0f, ss = 0.0f;
                const float* Mrow = &gs->Ms[gtid * MPITCH];
                #pragma unroll
                for (int v = 0; v < VV; ++v) {
                    float m = Mrow[v];
                    dr = fmaf(m, gs->kr[v], dr);
                    dw = fmaf(m, gs->kw[v], dw);
                    ss = fmaf(m, m, ss);
                }
                gs->dotr[gtid] = dr; gs->dotw[gtid] = dw; gs->mnorm[gtid] = sqrtf(ss);
            }
            if (gtid == 96) {
                float a0 = gs->praw[0], a1 = gs->praw[1], a2 = gs->praw[2];
                float m = fmaxf(a0, fmaxf(a1, a2));
                float e0 = __expf(a0 - m), e1 = __expf(a1 - m), e2 = __expf(a2 - m);
                float s = e0 + e1 + e2;
                gs->scal[3] = e0 / s; gs->scal[4] = e1 / s; gs->scal[5] = e2 / s;
            } else if (gtid == 97) {
                float s2 = 0.0f;
                #pragma unroll
                for (int v = 0; v < VV; ++v) s2 = fmaf(gs->kr[v], gs->kr[v], s2);
                gs->knorm[0] = sqrtf(s2);
            } else if (gtid == 98) {
                float a0 = gs->praw[3], a1 = gs->praw[4], a2 = gs->praw[5];
                float m = fmaxf(a0, fmaxf(a1, a2));
                float e0 = __expf(a0 - m), e1 = __expf(a1 - m), e2 = __expf(a2 - m);
                float s = e0 + e1 + e2;
                gs->scal[9] = e0 / s; gs->scal[10] = e1 / s; gs->scal[11] = e2 / s;
            } else if (gtid == 99) {
                float s2 = 0.0f;
                #pragma unroll
                for (int v = 0; v < VV; ++v) s2 = fmaf(gs->kw[v], gs->kw[v], s2);
                gs->knorm[1] = sqrtf(s2);
            }
            gbar(group);

            // ---- E: dual-head content softmax ----
            const float beta_r = gs->scal[0], g_r = gs->scal[1], gamma_r = gs->scal[2];
            const float s0r = gs->scal[3], s1r = gs->scal[4], s2r = gs->scal[5];
            const float beta_w = gs->scal[6], g_w = gs->scal[7], gamma_w = gs->scal[8];
            const float s0w = gs->scal[9], s1w = gs->scal[10], s2w = gs->scal[11];
            const float mn = gs->mnorm[gtid];
            float zr = beta_r * __fdividef(gs->dotr[gtid], fmaf(gs->knorm[0], mn, EPSF));
            float zw = beta_w * __fdividef(gs->dotw[gtid], fmaf(gs->knorm[1], mn, EPSF));
            float mr = zr, mw = zw;
            #pragma unroll
            for (int o = 16; o; o >>= 1) {
                mr = fmaxf(mr, __shfl_xor_sync(0xffffffffu, mr, o));
                mw = fmaxf(mw, __shfl_xor_sync(0xffffffffu, mw, o));
            }
            if (lane == 0) { gs->redA[gwid] = mr; gs->redB[gwid] = mw; }
            gbar(group);
            mr = fmaxf(fmaxf(gs->redA[0], gs->redA[1]), fmaxf(gs->redA[2], gs->redA[3]));
            mw = fmaxf(fmaxf(gs->redB[0], gs->redB[1]), fmaxf(gs->redB[2], gs->redB[3]));
            float er = __expf(zr - mr), ew = __expf(zw - mw);
            float sr = er, sw = ew;
            #pragma unroll
            for (int o = 16; o; o >>= 1) {
                sr += __shfl_xor_sync(0xffffffffu, sr, o);
                sw += __shfl_xor_sync(0xffffffffu, sw, o);
            }
            gbar(group);
            if (lane == 0) { gs->redA[gwid] = sr; gs->redB[gwid] = sw; }
            gbar(group);
            const float wcr = __fdividef(er, gs->redA[0] + gs->redA[1] + gs->redA[2] + gs->redA[3]);
            const float wcw = __fdividef(ew, gs->redB[0] + gs->redB[1] + gs->redB[2] + gs->redB[3]);

            // ---- F: read-head interpolation, shift, sharpen ----
            gs->wg[gtid] = fmaf(g_r, wcr - gs->wprev[gtid], gs->wprev[gtid]);
            gbar(group);
            {
                float ws = s0r * gs->wg[(gtid + 1) & (NN - 1)] + s1r * gs->wg[gtid]
                         + s2r * gs->wg[(gtid + NN - 1) & (NN - 1)];
                float wpow = (ws > 0.0f) ? ex2_(gamma_r * __log2f(ws)) : 0.0f;
                float sp = wpow;
                #pragma unroll
                for (int o = 16; o; o >>= 1) sp += __shfl_xor_sync(0xffffffffu, sp, o);
                if (lane == 0) gs->redA[gwid] = sp;
                gbar(group);
                sp = gs->redA[0] + gs->redA[1] + gs->redA[2] + gs->redA[3];
                gs->wr[gtid] = __fdividef(wpow, sp + EPSF);
            }
            gbar(group);

            // ---- G: r = wr @ M (80 thr) || write-head interpolation (all) ----
            gs->wg[gtid] = fmaf(g_w, wcw - gs->wr[gtid], gs->wr[gtid]);
            if (gtid < 80) {
                const int v = gtid % 20, q = gtid / 20;
                const int base = q * 32;
                float acc = 0.0f;
                #pragma unroll 8
                for (int j = 0; j < 32; ++j)
                    acc = fmaf(gs->wr[base + j], gs->Ms[(base + j) * MPITCH + v], acc);
                gs->part[gtid] = acc;
            }
            gbar(group);

            // ---- H: write-head shift+sharpen || r combine ----
            float wpoww;
            {
                float ws = s0w * gs->wg[(gtid + 1) & (NN - 1)] + s1w * gs->wg[gtid]
                         + s2w * gs->wg[(gtid + NN - 1) & (NN - 1)];
                wpoww = (ws > 0.0f) ? ex2_(gamma_w * __log2f(ws)) : 0.0f;
                float sp = wpoww;
                #pragma unroll
                for (int o = 16; o; o >>= 1) sp += __shfl_xor_sync(0xffffffffu, sp, o);
                if (lane == 0) gs->redB[gwid] = sp;
            }
            if (gtid < VV)
                gs->cat[II + gtid] = gs->part[gtid] + gs->part[20 + gtid]
                                   + gs->part[40 + gtid] + gs->part[60 + gtid];
            gbar(group);

            // ---- I: finalize ww + M update || output partials ----
            {
                float sp = gs->redB[0] + gs->redB[1] + gs->redB[2] + gs->redB[3];
                float ww = __fdividef(wpoww, sp + EPSF);
                gs->wprev[gtid] = ww;
                float* Mrow = &gs->Ms[gtid * MPITCH];
                #pragma unroll
                for (int v = 0; v < VV; ++v) {
                    float m = Mrow[v];
                    Mrow[v] = fmaf(ww, gs->av[v] - gs->ev[v] * m, m);
                }
            }
            if (gtid < 64) {
                const int o = gtid & 7, seg = gtid >> 3;
                float acc = 0.0f;
                #pragma unroll
                for (int j = seg * 15; j < seg * 15 + 15; ++j) {
                    float v = (j < CC) ? gs->h[j] : gs->cat[II + (j - CC)];
                    acc = fmaf(v, Wfs[j * 8 + o], acc);
                }
                gs->part[gtid] = acc;
            }
            gbar(group);

            // ---- J: output store || prefetch x_{t+1} ----
            if (gtid < OO) {
                float s = bfs[gtid];
                #pragma unroll
                for (int q = 0; q < 8; ++q) s += gs->part[q * 8 + gtid];
                ob[t * OO + gtid] = sigmoidf_(s);
            }
            if (gtid >= 96 && gtid < 96 + II && t + 1 < TT)
                gs->cat[gtid - 96] = xb[(t + 1) * II + (gtid - 96)];
            gbar(group);
        }
        gbar(group);
    }
}

extern "C" void kernel_launch(void* const* d_in, const int* in_sizes, int n_in,
                              void* d_out, int out_size) {
    const float* x      = (const float*)d_in[0];
    const float* Wc     = (const float*)d_in[1];
    const float* bc     = (const float*)d_in[2];
    const float* Wr     = (const float*)d_in[3];
    const float* br     = (const float*)d_in[4];
    const float* Ww     = (const float*)d_in[5];
    const float* bw     = (const float*)d_in[6];
    const float* Wf     = (const float*)d_in[7];
    const float* bf     = (const float*)d_in[8];
    const float* r_bias = (const float*)d_in[9];
    const float* M_bias = (const float*)d_in[10];
    float* out = (float*)d_out;

    const int Btot = in_sizes[0] / (TT * II);
    cudaFuncSetAttribute(ntm_kernel, cudaFuncAttributeMaxDynamicSharedMemorySize,
                         DYN_SMEM_BYTES);
    int grid = (Btot + 1) / 2;              // 2 batch elems per CTA, concurrent groups
    if (grid < 1) grid = 1;
    ntm_kernel<<<grid, 256, DYN_SMEM_BYTES>>>(x, Wc, bc, Wr, br, Ww, bw, Wf, bf,
                                              r_bias, M_bias, out, Btot);
}

// round 7
// speedup vs baseline: 1.7623x; 1.3738x over previous
#include <cuda_runtime.h>

// NTM forward: B=2048, T=64, I=9, N=128, V=20, S=3, C=100, O=8
#define TT 64
#define II 9
#define NN 128
#define VV 20
#define CC 100
#define OO 8
#define MPITCH 21
#define EPSF 1e-8f

// smem weight layout (floats)
#define WC_OFF 0            // 29*100 = 2900
#define WR_OFF 2900         // 100*26 = 2600
#define WW_OFF 5500         // 100*66 = 6600
#define WF_OFF 12100        // 120*8  = 960
#define BC_OFF 13060        // 100
#define BR_OFF 13160        // 26
#define BW_OFF 13186        // 66
#define BF_OFF 13252        // 8
#define GS_OFF 13260

#define NGROUPS 8
#define GTHREADS 64

struct GroupState {
    float Ms[NN * MPITCH];      // 2688
    float cat[32];              // [x(9), r(20)]
    float h[CC];
    float kr[VV], kw[VV], ev[VV], av[VV];
    float wprev[NN], wr[NN], wg[NN];
    float part[80];
    float redA[2], redB[2], redC[2], redD[2];
    float scal[12];             // beta_r,g_r,gamma_r,s_r(3), beta_w,g_w,gamma_w,s_w(3)
    float praw[6];
    float knorm[2];
};

#define DYN_SMEM_BYTES ((GS_OFF + NGROUPS * (int)(sizeof(GroupState) / 4)) * 4)

__device__ __forceinline__ float sigmoidf_(float x) {
    return 1.0f / (1.0f + __expf(-x));
}
__device__ __forceinline__ float softplusf_(float x) {
    return fmaxf(x, 0.0f) + log1pf(__expf(-fabsf(x)));
}
__device__ __forceinline__ float ex2_(float x) {
    float r;
    asm("ex2.approx.ftz.f32 %0, %1;" : "=f"(r) : "f"(x));
    return r;
}
__device__ __forceinline__ void gbar(int g) {   // 64-thread group barrier
    asm volatile("bar.sync %0, 64;" :: "r"(g + 1) : "memory");
}

__device__ __forceinline__ void head_dispatch(GroupState* gs, int o, float acc) {
    if (o < 20)       gs->kr[o] = tanhf(acc);
    else if (o == 20) gs->scal[0] = softplusf_(acc);
    else if (o == 21) gs->scal[1] = sigmoidf_(acc);
    else if (o < 25)  gs->praw[o - 22] = acc;
    else if (o == 25) gs->scal[2] = 1.0f + softplusf_(acc);
    else if (o < 46)  gs->kw[o - 26] = tanhf(acc);
    else if (o == 46) gs->scal[6] = softplusf_(acc);
    else if (o == 47) gs->scal[7] = sigmoidf_(acc);
    else if (o < 51)  gs->praw[3 + o - 48] = acc;
    else if (o == 51) gs->scal[8] = 1.0f + softplusf_(acc);
    else if (o < 72)  gs->ev[o - 52] = sigmoidf_(acc);
    else              gs->av[o - 72] = tanhf(acc);
}

__global__ __launch_bounds__(512, 1) void ntm_kernel(
    const float* __restrict__ x,
    const float* __restrict__ Wc, const float* __restrict__ bc,
    const float* __restrict__ Wr, const float* __restrict__ br,
    const float* __restrict__ Ww, const float* __restrict__ bw,
    const float* __restrict__ Wf, const float* __restrict__ bf,
    const float* __restrict__ r_bias, const float* __restrict__ M_bias,
    float* __restrict__ out, int Btot)
{
    extern __shared__ float sm[];

    const int tid = threadIdx.x;
    // ---- one-time weight+bias load into smem ----
    for (int i = tid; i < 2900; i += 512) sm[WC_OFF + i] = Wc[i];
    for (int i = tid; i < 2600; i += 512) sm[WR_OFF + i] = Wr[i];
    for (int i = tid; i < 6600; i += 512) sm[WW_OFF + i] = Ww[i];
    for (int i = tid; i < 960;  i += 512) sm[WF_OFF + i] = Wf[i];
    for (int i = tid; i < 100;  i += 512) sm[BC_OFF + i] = bc[i];
    for (int i = tid; i < 26;   i += 512) sm[BR_OFF + i] = br[i];
    for (int i = tid; i < 66;   i += 512) sm[BW_OFF + i] = bw[i];
    for (int i = tid; i < 8;    i += 512) sm[BF_OFF + i] = bf[i];
    __syncthreads();

    const int group = tid >> 6;           // 0..7
    const int gtid = tid & 63;            // 0..63
    const int lane = tid & 31;
    const int gw = gtid >> 5;             // warp within group: 0/1
    GroupState* gs = reinterpret_cast<GroupState*>(sm + GS_OFF) + group;

    const float* Wcs = sm + WC_OFF; const float* Wrs = sm + WR_OFF;
    const float* Wws = sm + WW_OFF; const float* Wfs = sm + WF_OFF;
    const float* bcs = sm + BC_OFF; const float* brs = sm + BR_OFF;
    const float* bws = sm + BW_OFF; const float* bfs = sm + BF_OFF;

    const int r0 = gtid, r1 = gtid + 64;  // this thread's memory rows

    for (int b = blockIdx.x * NGROUPS + group; b < Btot; b += gridDim.x * NGROUPS) {
        // ---- init state ----
        for (int idx = gtid; idx < NN * VV; idx += GTHREADS)
            gs->Ms[(idx / VV) * MPITCH + (idx % VV)] = M_bias[idx];
        if (gtid < VV) gs->cat[II + gtid] = r_bias[gtid];
        gs->wprev[r0] = 0.0f; gs->wprev[r1] = 0.0f;

        const float* xb = x + (size_t)b * TT * II;
        float* ob = out + (size_t)b * TT * OO;
        if (gtid < II) gs->cat[gtid] = xb[gtid];
        gbar(group);

        for (int t = 0; t < TT; ++t) {
            // ---- B: controller h = tanh(cat @ Wc + bc), 100 outs over 64 thr ----
            {
                float acc0 = bcs[gtid];
                float acc1 = (gtid < 36) ? bcs[gtid + 64] : 0.0f;
                #pragma unroll
                for (int i = 0; i < II + VV; ++i) {
                    float ci = gs->cat[i];
                    acc0 = fmaf(ci, Wcs[i * CC + gtid], acc0);
                    if (gtid < 36) acc1 = fmaf(ci, Wcs[i * CC + gtid + 64], acc1);
                }
                gs->h[gtid] = tanhf(acc0);
                if (gtid < 36) gs->h[gtid + 64] = tanhf(acc1);
            }
            gbar(group);

            // ---- C: head pre-activations (92 outs) + fused nonlinearity ----
            {
                float acc0, acc1 = 0.0f;
                const int o0 = gtid, o1 = gtid + 64;
                acc0 = (o0 < 26) ? brs[o0] : bws[o0 - 26];
                if (o1 < 92) acc1 = bws[o1 - 26];
                #pragma unroll 4
                for (int c = 0; c < CC; ++c) {
                    float hc = gs->h[c];
                    acc0 = fmaf(hc, (o0 < 26) ? Wrs[c * 26 + o0] : Wws[c * 66 + (o0 - 26)], acc0);
                    if (o1 < 92) acc1 = fmaf(hc, Wws[c * 66 + (o1 - 26)], acc1);
                }
                head_dispatch(gs, o0, acc0);
                if (o1 < 92) head_dispatch(gs, o1, acc1);
            }
            gbar(group);

            // ---- D: fused pass over M (2 rows/thread) + side jobs ----
            float dr0 = 0.0f, dw0 = 0.0f, ss0 = 0.0f;
            float dr1 = 0.0f, dw1 = 0.0f, ss1 = 0.0f;
            {
                const float* M0 = &gs->Ms[r0 * MPITCH];
                const float* M1 = &gs->Ms[r1 * MPITCH];
                #pragma unroll
                for (int v = 0; v < VV; ++v) {
                    float krv = gs->kr[v], kwv = gs->kw[v];
                    float m0 = M0[v], m1 = M1[v];
                    dr0 = fmaf(m0, krv, dr0); dw0 = fmaf(m0, kwv, dw0); ss0 = fmaf(m0, m0, ss0);
                    dr1 = fmaf(m1, krv, dr1); dw1 = fmaf(m1, kwv, dw1); ss1 = fmaf(m1, m1, ss1);
                }
            }
            const float mn0 = sqrtf(ss0), mn1 = sqrtf(ss1);
            if (gtid == 40) {                      // s_r softmax(3)
                float a0 = gs->praw[0], a1 = gs->praw[1], a2 = gs->praw[2];
                float m = fmaxf(a0, fmaxf(a1, a2));
                float e0 = __expf(a0 - m), e1 = __expf(a1 - m), e2 = __expf(a2 - m);
                float s = e0 + e1 + e2;
                gs->scal[3] = e0 / s; gs->scal[4] = e1 / s; gs->scal[5] = e2 / s;
            } else if (gtid == 41) {               // |kr|
                float s2 = 0.0f;
                #pragma unroll
                for (int v = 0; v < VV; ++v) s2 = fmaf(gs->kr[v], gs->kr[v], s2);
                gs->knorm[0] = sqrtf(s2);
            } else if (gtid == 42) {               // s_w softmax(3)
                float a0 = gs->praw[3], a1 = gs->praw[4], a2 = gs->praw[5];
                float m = fmaxf(a0, fmaxf(a1, a2));
                float e0 = __expf(a0 - m), e1 = __expf(a1 - m), e2 = __expf(a2 - m);
                float s = e0 + e1 + e2;
                gs->scal[9] = e0 / s; gs->scal[10] = e1 / s; gs->scal[11] = e2 / s;
            } else if (gtid == 43) {               // |kw|
                float s2 = 0.0f;
                #pragma unroll
                for (int v = 0; v < VV; ++v) s2 = fmaf(gs->kw[v], gs->kw[v], s2);
                gs->knorm[1] = sqrtf(s2);
            }
            gbar(group);

            // ---- E: dual-head content softmax (2 rows/thread) ----
            const float beta_r = gs->scal[0], g_r = gs->scal[1], gamma_r = gs->scal[2];
            const float s0r = gs->scal[3], s1r = gs->scal[4], s2r = gs->scal[5];
            const float beta_w = gs->scal[6], g_w = gs->scal[7], gamma_w = gs->scal[8];
            const float s0w = gs->scal[9], s1w = gs->scal[10], s2w = gs->scal[11];
            const float knr = gs->knorm[0], knw = gs->knorm[1];
            float zr0 = beta_r * __fdividef(dr0, fmaf(knr, mn0, EPSF));
            float zr1 = beta_r * __fdividef(dr1, fmaf(knr, mn1, EPSF));
            float zw0 = beta_w * __fdividef(dw0, fmaf(knw, mn0, EPSF));
            float zw1 = beta_w * __fdividef(dw1, fmaf(knw, mn1, EPSF));
            float mr = fmaxf(zr0, zr1), mw = fmaxf(zw0, zw1);
            #pragma unroll
            for (int o = 16; o; o >>= 1) {
                mr = fmaxf(mr, __shfl_xor_sync(0xffffffffu, mr, o));
                mw = fmaxf(mw, __shfl_xor_sync(0xffffffffu, mw, o));
            }
            if (lane == 0) { gs->redA[gw] = mr; gs->redB[gw] = mw; }
            gbar(group);
            mr = fmaxf(gs->redA[0], gs->redA[1]);
            mw = fmaxf(gs->redB[0], gs->redB[1]);
            float er0 = __expf(zr0 - mr), er1 = __expf(zr1 - mr);
            float ew0 = __expf(zw0 - mw), ew1 = __expf(zw1 - mw);
            float sr = er0 + er1, sw = ew0 + ew1;
            #pragma unroll
            for (int o = 16; o; o >>= 1) {
                sr += __shfl_xor_sync(0xffffffffu, sr, o);
                sw += __shfl_xor_sync(0xffffffffu, sw, o);
            }
            if (lane == 0) { gs->redC[gw] = sr; gs->redD[gw] = sw; }
            gbar(group);
            {
                float isr = __fdividef(1.0f, gs->redC[0] + gs->redC[1]);
                float isw = __fdividef(1.0f, gs->redD[0] + gs->redD[1]);
                float wcr0 = er0 * isr, wcr1 = er1 * isr;
                // read-head interpolation
                gs->wg[r0] = fmaf(g_r, wcr0 - gs->wprev[r0], gs->wprev[r0]);
                gs->wg[r1] = fmaf(g_r, wcr1 - gs->wprev[r1], gs->wprev[r1]);
                // stash write-head content weights in regs for phase G
                er0 = ew0 * isw; er1 = ew1 * isw;    // reuse er regs = wcw0, wcw1
            }
            gbar(group);

            // ---- F: read-head shift + sharpen ----
            {
                float ws0 = s0r * gs->wg[(r0 + 1) & (NN - 1)] + s1r * gs->wg[r0]
                          + s2r * gs->wg[(r0 + NN - 1) & (NN - 1)];
                float ws1 = s0r * gs->wg[(r1 + 1) & (NN - 1)] + s1r * gs->wg[r1]
                          + s2r * gs->wg[(r1 + NN - 1) & (NN - 1)];
                float wp0 = (ws0 > 0.0f) ? ex2_(gamma_r * __log2f(ws0)) : 0.0f;
                float wp1 = (ws1 > 0.0f) ? ex2_(gamma_r * __log2f(ws1)) : 0.0f;
                float sp = wp0 + wp1;
                #pragma unroll
                for (int o = 16; o; o >>= 1) sp += __shfl_xor_sync(0xffffffffu, sp, o);
                if (lane == 0) gs->redA[gw] = sp;
                gbar(group);
                float isp = __fdividef(1.0f, gs->redA[0] + gs->redA[1] + EPSF);
                gs->wr[r0] = wp0 * isp;
                gs->wr[r1] = wp1 * isp;
            }
            gbar(group);

            // ---- G: write-head interpolation (wg) || r = wr @ M (60 thr) ----
            gs->wg[r0] = fmaf(g_w, er0 - gs->wr[r0], gs->wr[r0]);
            gs->wg[r1] = fmaf(g_w, er1 - gs->wr[r1], gs->wr[r1]);
            if (gtid < 60) {
                const int v = gtid % 20, q = gtid / 20;      // 3 segs: 43,43,42 rows
                const int beg = q * 43, end = (q == 2) ? NN : beg + 43;
                float acc = 0.0f;
                for (int j = beg; j < end; ++j)
                    acc = fmaf(gs->wr[j], gs->Ms[j * MPITCH + v], acc);
                gs->part[q * 20 + v] = acc;
            }
            gbar(group);

            // ---- H: write-head shift + sharpen || r combine ----
            float wpw0, wpw1;
            {
                float ws0 = s0w * gs->wg[(r0 + 1) & (NN - 1)] + s1w * gs->wg[r0]
                          + s2w * gs->wg[(r0 + NN - 1) & (NN - 1)];
                float ws1 = s0w * gs->wg[(r1 + 1) & (NN - 1)] + s1w * gs->wg[r1]
                          + s2w * gs->wg[(r1 + NN - 1) & (NN - 1)];
                wpw0 = (ws0 > 0.0f) ? ex2_(gamma_w * __log2f(ws0)) : 0.0f;
                wpw1 = (ws1 > 0.0f) ? ex2_(gamma_w * __log2f(ws1)) : 0.0f;
                float sp = wpw0 + wpw1;
                #pragma unroll
                for (int o = 16; o; o >>= 1) sp += __shfl_xor_sync(0xffffffffu, sp, o);
                if (lane == 0) gs->redB[gw] = sp;
            }
            if (gtid < VV)
                gs->cat[II + gtid] = gs->part[gtid] + gs->part[20 + gtid] + gs->part[40 + gtid];
            gbar(group);

            // ---- I: finalize ww + M update (2 rows) || output partials ----
            {
                float isp = __fdividef(1.0f, gs->redB[0] + gs->redB[1] + EPSF);
                float ww0 = wpw0 * isp, ww1 = wpw1 * isp;
                gs->wprev[r0] = ww0; gs->wprev[r1] = ww1;
                float* M0 = &gs->Ms[r0 * MPITCH];
                float* M1 = &gs->Ms[r1 * MPITCH];
                #pragma unroll
                for (int v = 0; v < VV; ++v) {
                    float ev_ = gs->ev[v], av_ = gs->av[v];
                    float m0 = M0[v], m1 = M1[v];
                    M0[v] = fmaf(ww0, av_ - ev_ * m0, m0);
                    M1[v] = fmaf(ww1, av_ - ev_ * m1, m1);
                }
            }
            {
                const int o = gtid & 7, seg = gtid >> 3;      // 8 segs of 15
                float acc = 0.0f;
                #pragma unroll
                for (int j = seg * 15; j < seg * 15 + 15; ++j) {
                    float v = (j < CC) ? gs->h[j] : gs->cat[II + (j - CC)];
                    acc = fmaf(v, Wfs[j * 8 + o], acc);
                }
                gs->part[gtid] = acc;
            }
            gbar(group);

            // ---- J: output store || prefetch x_{t+1} ----
            if (gtid < OO) {
                float s = bfs[gtid];
                #pragma unroll
                for (int q = 0; q < 8; ++q) s += gs->part[q * 8 + gtid];
                ob[t * OO + gtid] = sigmoidf_(s);
            }
            if (gtid >= 40 && gtid < 40 + II && t + 1 < TT)
                gs->cat[gtid - 40] = xb[(t + 1) * II + (gtid - 40)];
            gbar(group);
        }
        gbar(group);
    }
}

extern "C" void kernel_launch(void* const* d_in, const int* in_sizes, int n_in,
                              void* d_out, int out_size) {
    const float* x      = (const float*)d_in[0];
    const float* Wc     = (const float*)d_in[1];
    const float* bc     = (const float*)d_in[2];
    const float* Wr     = (const float*)d_in[3];
    const float* br     = (const float*)d_in[4];
    const float* Ww     = (const float*)d_in[5];
    const float* bw     = (const float*)d_in[6];
    const float* Wf     = (const float*)d_in[7];
    const float* bf     = (const float*)d_in[8];
    const float* r_bias = (const float*)d_in[9];
    const float* M_bias = (const float*)d_in[10];
    float* out = (float*)d_out;

    const int Btot = in_sizes[0] / (TT * II);
    cudaFuncSetAttribute(ntm_kernel, cudaFuncAttributeMaxDynamicSharedMemorySize,
                         DYN_SMEM_BYTES);
    int grid = (Btot + NGROUPS - 1) / NGROUPS;   // 8 concurrent batches per CTA
    if (grid < 1) grid = 1;
    ntm_kernel<<<grid, 512, DYN_SMEM_BYTES>>>(x, Wc, bc, Wr, br, Ww, bw, Wf, bf,
                                              r_bias, M_bias, out, Btot);
}

// round 8
// speedup vs baseline: 2.1736x; 1.2334x over previous
#include <cuda_runtime.h>

// NTM forward: B=2048, T=64, I=9, N=128, V=20, S=3, C=100, O=8
#define TT 64
#define II 9
#define NN 128
#define VV 20
#define CC 100
#define OO 8
#define MP 22               // M row pitch (float2-friendly, conflict-free at stride 22)
#define EPSF 1e-8f

// smem weight layout (floats) — transposed rows, contiguous per output neuron
#define WCT_OFF 0            // 100 rows x 36 (Wc^T, padded 29->36, zero pad)
#define WRT_OFF 3600         // 26 rows x 100 (Wr^T)
#define WWT_OFF 6200         // 66 rows x 100 (Ww^T)
#define WF_OFF  12800        // 120 x 8 (original layout — conflict-free as-is)
#define BC_OFF  13760        // 100
#define BR_OFF  13860        // 26
#define BW_OFF  13886        // 66
#define BF_OFF  13952        // 8
#define GS_OFF  13960        // 16B-aligned

#define NGROUPS 8
#define GTHREADS 64

struct GroupState {
    float Ms[NN * MP];          // 2816 (16B-aligned base)
    float cat[32];              // [x(9), r(20), zeropad(3)] — 16B aligned
    float h[104];               // 100 used
    float kr[VV], kw[VV], ev[VV], av[VV];
    float wprev[NN], wr[NN], wg[NN];
    float part[80];
    float redA[2], redB[2];
    float scal[12];             // beta_r,g_r,gamma_r,s_r(3), beta_w,g_w,gamma_w,s_w(3)
    float praw[6];
    float knorm[2];
};                               // 3520 floats (mult of 4)

#define DYN_SMEM_BYTES ((GS_OFF + NGROUPS * (int)(sizeof(GroupState) / 4)) * 4)

__device__ __forceinline__ float sigmoidf_(float x) {
    return 1.0f / (1.0f + __expf(-x));
}
__device__ __forceinline__ float softplusf_(float x) {
    return fmaxf(x, 0.0f) + log1pf(__expf(-fabsf(x)));
}
__device__ __forceinline__ float ex2_(float x) {
    float r;
    asm("ex2.approx.ftz.f32 %0, %1;" : "=f"(r) : "f"(x));
    return r;
}
__device__ __forceinline__ void gbar(int g) {   // 64-thread group barrier
    asm volatile("bar.sync %0, 64;" :: "r"(g + 1) : "memory");
}
__device__ __forceinline__ float dot4(const float4 a, const float4 b, float acc) {
    acc = fmaf(a.x, b.x, acc); acc = fmaf(a.y, b.y, acc);
    acc = fmaf(a.z, b.z, acc); acc = fmaf(a.w, b.w, acc);
    return acc;
}

__device__ __forceinline__ void head_dispatch(GroupState* gs, int o, float acc) {
    if (o < 20)       gs->kr[o] = tanhf(acc);
    else if (o == 20) gs->scal[0] = softplusf_(acc);
    else if (o == 21) gs->scal[1] = sigmoidf_(acc);
    else if (o < 25)  gs->praw[o - 22] = acc;
    else if (o == 25) gs->scal[2] = 1.0f + softplusf_(acc);
    else if (o < 46)  gs->kw[o - 26] = tanhf(acc);
    else if (o == 46) gs->scal[6] = softplusf_(acc);
    else if (o == 47) gs->scal[7] = sigmoidf_(acc);
    else if (o < 51)  gs->praw[3 + o - 48] = acc;
    else if (o == 51) gs->scal[8] = 1.0f + softplusf_(acc);
    else if (o < 72)  gs->ev[o - 52] = sigmoidf_(acc);
    else              gs->av[o - 72] = tanhf(acc);
}

__global__ __launch_bounds__(512, 1) void ntm_kernel(
    const float* __restrict__ x,
    const float* __restrict__ Wc, const float* __restrict__ bc,
    const float* __restrict__ Wr, const float* __restrict__ br,
    const float* __restrict__ Ww, const float* __restrict__ bw,
    const float* __restrict__ Wf, const float* __restrict__ bf,
    const float* __restrict__ r_bias, const float* __restrict__ M_bias,
    float* __restrict__ out, int Btot)
{
    extern __shared__ float sm[];

    const int tid = threadIdx.x;
    // ---- one-time transposed weight load ----
    for (int i = tid; i < 3600; i += 512) sm[WCT_OFF + i] = 0.0f;   // zero pad cols
    __syncthreads();
    for (int i = tid; i < 2900; i += 512) {          // WcT[j*36+i] = Wc[i*100+j]
        int r = i / 100, c = i % 100;                // r<29, c<100
        sm[WCT_OFF + c * 36 + r] = Wc[i];
    }
    for (int i = tid; i < 2600; i += 512) {          // WrT[o*100+c] = Wr[c*26+o]
        int c = i / 26, o = i % 26;
        sm[WRT_OFF + o * 100 + c] = Wr[i];
    }
    for (int i = tid; i < 6600; i += 512) {          // WwT[o*100+c] = Ww[c*66+o]
        int c = i / 66, o = i % 66;
        sm[WWT_OFF + o * 100 + c] = Ww[i];
    }
    for (int i = tid; i < 960;  i += 512) sm[WF_OFF + i] = Wf[i];
    for (int i = tid; i < 100;  i += 512) sm[BC_OFF + i] = bc[i];
    for (int i = tid; i < 26;   i += 512) sm[BR_OFF + i] = br[i];
    for (int i = tid; i < 66;   i += 512) sm[BW_OFF + i] = bw[i];
    for (int i = tid; i < 8;    i += 512) sm[BF_OFF + i] = bf[i];
    __syncthreads();

    const int group = tid >> 6;           // 0..7
    const int gtid = tid & 63;            // 0..63
    const int lane = tid & 31;
    const int gw = gtid >> 5;             // warp within group: 0/1
    GroupState* gs = reinterpret_cast<GroupState*>(sm + GS_OFF) + group;

    const float* Wfs = sm + WF_OFF;
    const float* bcs = sm + BC_OFF; const float* brs = sm + BR_OFF;
    const float* bws = sm + BW_OFF; const float* bfs = sm + BF_OFF;

    const int r0 = gtid, r1 = gtid + 64;  // this thread's memory rows

    for (int b = blockIdx.x * NGROUPS + group; b < Btot; b += gridDim.x * NGROUPS) {
        // ---- init state ----
        for (int idx = gtid; idx < NN * VV; idx += GTHREADS)
            gs->Ms[(idx / VV) * MP + (idx % VV)] = M_bias[idx];
        if (gtid < VV) gs->cat[II + gtid] = r_bias[gtid];
        if (gtid >= 29 && gtid < 32) gs->cat[gtid] = 0.0f;   // zero pad (i=29..31)
        gs->wprev[r0] = 0.0f; gs->wprev[r1] = 0.0f;

        const float* xb = x + (size_t)b * TT * II;
        float* ob = out + (size_t)b * TT * OO;
        if (gtid < II) gs->cat[gtid] = xb[gtid];
        gbar(group);

        for (int t = 0; t < TT; ++t) {
            // ---- B: controller h = tanh(cat @ Wc + bc), vectorized ----
            {
                const float4* cat4 = reinterpret_cast<const float4*>(gs->cat);
                const float4* w0 = reinterpret_cast<const float4*>(sm + WCT_OFF + gtid * 36);
                const float4* w1 = reinterpret_cast<const float4*>(sm + WCT_OFF + (gtid + 64) * 36);
                float acc0 = bcs[gtid];
                float acc1 = (gtid < 36) ? bcs[gtid + 64] : 0.0f;
                #pragma unroll
                for (int k = 0; k < 8; ++k) {        // covers i=0..31 (pad is zero)
                    float4 cv = cat4[k];
                    acc0 = dot4(cv, w0[k], acc0);
                    if (gtid < 36) acc1 = dot4(cv, w1[k], acc1);
                }
                gs->h[gtid] = tanhf(acc0);
                if (gtid < 36) gs->h[gtid + 64] = tanhf(acc1);
            }
            gbar(group);

            // ---- C: head pre-activations (92 outs), vectorized ----
            {
                const int o0 = gtid, o1 = gtid + 64;
                const float4* h4 = reinterpret_cast<const float4*>(gs->h);
                const float4* w0 = reinterpret_cast<const float4*>(
                    (o0 < 26) ? (sm + WRT_OFF + o0 * 100) : (sm + WWT_OFF + (o0 - 26) * 100));
                const float4* w1 = reinterpret_cast<const float4*>(
                    sm + WWT_OFF + (o1 - 26) * 100);
                float acc0 = (o0 < 26) ? brs[o0] : bws[o0 - 26];
                float acc1 = (o1 < 92) ? bws[o1 - 26] : 0.0f;
                const bool has1 = (o1 < 92);
                #pragma unroll 5
                for (int k = 0; k < 25; ++k) {       // c = 0..99
                    float4 hv = h4[k];
                    acc0 = dot4(hv, w0[k], acc0);
                    if (has1) acc1 = dot4(hv, w1[k], acc1);
                }
                head_dispatch(gs, o0, acc0);
                if (has1) head_dispatch(gs, o1, acc1);
            }
            gbar(group);

            // ---- D: fused pass over M (2 rows/thread, float2) + side jobs ----
            float dr0 = 0.0f, dw0 = 0.0f, ss0 = 0.0f;
            float dr1 = 0.0f, dw1 = 0.0f, ss1 = 0.0f;
            {
                const float2* M0 = reinterpret_cast<const float2*>(&gs->Ms[r0 * MP]);
                const float2* M1 = reinterpret_cast<const float2*>(&gs->Ms[r1 * MP]);
                const float2* kr2 = reinterpret_cast<const float2*>(gs->kr);
                const float2* kw2 = reinterpret_cast<const float2*>(gs->kw);
                #pragma unroll
                for (int v = 0; v < VV / 2; ++v) {
                    float2 kvr = kr2[v], kvw = kw2[v];
                    float2 m0 = M0[v], m1 = M1[v];
                    dr0 = fmaf(m0.x, kvr.x, dr0); dr0 = fmaf(m0.y, kvr.y, dr0);
                    dw0 = fmaf(m0.x, kvw.x, dw0); dw0 = fmaf(m0.y, kvw.y, dw0);
                    ss0 = fmaf(m0.x, m0.x, ss0);  ss0 = fmaf(m0.y, m0.y, ss0);
                    dr1 = fmaf(m1.x, kvr.x, dr1); dr1 = fmaf(m1.y, kvr.y, dr1);
                    dw1 = fmaf(m1.x, kvw.x, dw1); dw1 = fmaf(m1.y, kvw.y, dw1);
                    ss1 = fmaf(m1.x, m1.x, ss1);  ss1 = fmaf(m1.y, m1.y, ss1);
                }
            }
            const float mn0 = sqrtf(ss0), mn1 = sqrtf(ss1);
            if (gtid == 40) {                      // s_r softmax(3)
                float a0 = gs->praw[0], a1 = gs->praw[1], a2 = gs->praw[2];
                float m = fmaxf(a0, fmaxf(a1, a2));
                float e0 = __expf(a0 - m), e1 = __expf(a1 - m), e2 = __expf(a2 - m);
                float s = e0 + e1 + e2;
                gs->scal[3] = e0 / s; gs->scal[4] = e1 / s; gs->scal[5] = e2 / s;
            } else if (gtid == 41) {               // |kr|
                float s2 = 0.0f;
                #pragma unroll
                for (int v = 0; v < VV; ++v) s2 = fmaf(gs->kr[v], gs->kr[v], s2);
                gs->knorm[0] = sqrtf(s2);
            } else if (gtid == 42) {               // s_w softmax(3)
                float a0 = gs->praw[3], a1 = gs->praw[4], a2 = gs->praw[5];
                float m = fmaxf(a0, fmaxf(a1, a2));
                float e0 = __expf(a0 - m), e1 = __expf(a1 - m), e2 = __expf(a2 - m);
                float s = e0 + e1 + e2;
                gs->scal[9] = e0 / s; gs->scal[10] = e1 / s; gs->scal[11] = e2 / s;
            } else if (gtid == 43) {               // |kw|
                float s2 = 0.0f;
                #pragma unroll
                for (int v = 0; v < VV; ++v) s2 = fmaf(gs->kw[v], gs->kw[v], s2);
                gs->knorm[1] = sqrtf(s2);
            }
            gbar(group);

            // ---- E: dual-head content softmax (no max pass; |z| <= ~5) ----
            const float beta_r = gs->scal[0], g_r = gs->scal[1], gamma_r = gs->scal[2];
            const float s0r = gs->scal[3], s1r = gs->scal[4], s2r = gs->scal[5];
            const float beta_w = gs->scal[6], g_w = gs->scal[7], gamma_w = gs->scal[8];
            const float s0w = gs->scal[9], s1w = gs->scal[10], s2w = gs->scal[11];
            const float knr = gs->knorm[0], knw = gs->knorm[1];
            float er0 = __expf(beta_r * __fdividef(dr0, fmaf(knr, mn0, EPSF)));
            float er1 = __expf(beta_r * __fdividef(dr1, fmaf(knr, mn1, EPSF)));
            float ew0 = __expf(beta_w * __fdividef(dw0, fmaf(knw, mn0, EPSF)));
            float ew1 = __expf(beta_w * __fdividef(dw1, fmaf(knw, mn1, EPSF)));
            float sr = er0 + er1, sw = ew0 + ew1;
            #pragma unroll
            for (int o = 16; o; o >>= 1) {
                sr += __shfl_xor_sync(0xffffffffu, sr, o);
                sw += __shfl_xor_sync(0xffffffffu, sw, o);
            }
            if (lane == 0) { gs->redA[gw] = sr; gs->redB[gw] = sw; }
            gbar(group);
            {
                float isr = __fdividef(1.0f, gs->redA[0] + gs->redA[1]);
                float isw = __fdividef(1.0f, gs->redB[0] + gs->redB[1]);
                float wcr0 = er0 * isr, wcr1 = er1 * isr;
                gs->wg[r0] = fmaf(g_r, wcr0 - gs->wprev[r0], gs->wprev[r0]);
                gs->wg[r1] = fmaf(g_r, wcr1 - gs->wprev[r1], gs->wprev[r1]);
                er0 = ew0 * isw; er1 = ew1 * isw;    // stash wcw0, wcw1
            }
            gbar(group);

            // ---- F: read-head shift + sharpen ----
            {
                float ws0 = s0r * gs->wg[(r0 + 1) & (NN - 1)] + s1r * gs->wg[r0]
                          + s2r * gs->wg[(r0 + NN - 1) & (NN - 1)];
                float ws1 = s0r * gs->wg[(r1 + 1) & (NN - 1)] + s1r * gs->wg[r1]
                          + s2r * gs->wg[(r1 + NN - 1) & (NN - 1)];
                float wp0 = (ws0 > 0.0f) ? ex2_(gamma_r * __log2f(ws0)) : 0.0f;
                float wp1 = (ws1 > 0.0f) ? ex2_(gamma_r * __log2f(ws1)) : 0.0f;
                float sp = wp0 + wp1;
                #pragma unroll
                for (int o = 16; o; o >>= 1) sp += __shfl_xor_sync(0xffffffffu, sp, o);
                if (lane == 0) gs->redA[gw] = sp;
                gbar(group);
                float isp = __fdividef(1.0f, gs->redA[0] + gs->redA[1] + EPSF);
                gs->wr[r0] = wp0 * isp;
                gs->wr[r1] = wp1 * isp;
            }
            gbar(group);

            // ---- G: write-head interpolation (wg) || r = wr @ M (60 thr) ----
            gs->wg[r0] = fmaf(g_w, er0 - gs->wr[r0], gs->wr[r0]);
            gs->wg[r1] = fmaf(g_w, er1 - gs->wr[r1], gs->wr[r1]);
            if (gtid < 60) {
                const int v = gtid % 20, q = gtid / 20;      // 3 segs: 43,43,42 rows
                const int beg = q * 43, end = (q == 2) ? NN : beg + 43;
                float acc = 0.0f;
                for (int j = beg; j < end; ++j)
                    acc = fmaf(gs->wr[j], gs->Ms[j * MP + v], acc);
                gs->part[q * 20 + v] = acc;
            }
            gbar(group);

            // ---- H: write-head shift + sharpen || r combine ----
            float wpw0, wpw1;
            {
                float ws0 = s0w * gs->wg[(r0 + 1) & (NN - 1)] + s1w * gs->wg[r0]
                          + s2w * gs->wg[(r0 + NN - 1) & (NN - 1)];
                float ws1 = s0w * gs->wg[(r1 + 1) & (NN - 1)] + s1w * gs->wg[r1]
                          + s2w * gs->wg[(r1 + NN - 1) & (NN - 1)];
                wpw0 = (ws0 > 0.0f) ? ex2_(gamma_w * __log2f(ws0)) : 0.0f;
                wpw1 = (ws1 > 0.0f) ? ex2_(gamma_w * __log2f(ws1)) : 0.0f;
                float sp = wpw0 + wpw1;
                #pragma unroll
                for (int o = 16; o; o >>= 1) sp += __shfl_xor_sync(0xffffffffu, sp, o);
                if (lane == 0) gs->redB[gw] = sp;
            }
            if (gtid < VV)
                gs->cat[II + gtid] = gs->part[gtid] + gs->part[20 + gtid] + gs->part[40 + gtid];
            gbar(group);

            // ---- I: finalize ww + M update (2 rows, float2) || output partials ----
            {
                float isp = __fdividef(1.0f, gs->redB[0] + gs->redB[1] + EPSF);
                float ww0 = wpw0 * isp, ww1 = wpw1 * isp;
                gs->wprev[r0] = ww0; gs->wprev[r1] = ww1;
                float2* M0 = reinterpret_cast<float2*>(&gs->Ms[r0 * MP]);
                float2* M1 = reinterpret_cast<float2*>(&gs->Ms[r1 * MP]);
                const float2* ev2 = reinterpret_cast<const float2*>(gs->ev);
                const float2* av2 = reinterpret_cast<const float2*>(gs->av);
                #pragma unroll
                for (int v = 0; v < VV / 2; ++v) {
                    float2 e = ev2[v], a = av2[v];
                    float2 m0 = M0[v], m1 = M1[v];
                    m0.x = fmaf(ww0, a.x - e.x * m0.x, m0.x);
                    m0.y = fmaf(ww0, a.y - e.y * m0.y, m0.y);
                    m1.x = fmaf(ww1, a.x - e.x * m1.x, m1.x);
                    m1.y = fmaf(ww1, a.y - e.y * m1.y, m1.y);
                    M0[v] = m0; M1[v] = m1;
                }
            }
            {
                const int o = gtid & 7, seg = gtid >> 3;      // 8 segs of 15
                float acc = 0.0f;
                #pragma unroll
                for (int j = seg * 15; j < seg * 15 + 15; ++j) {
                    float v = (j < CC) ? gs->h[j] : gs->cat[II + (j - CC)];
                    acc = fmaf(v, Wfs[j * 8 + o], acc);
                }
                gs->part[gtid] = acc;
            }
            gbar(group);

            // ---- J: output store || prefetch x_{t+1} ----
            if (gtid < OO) {
                float s = bfs[gtid];
                #pragma unroll
                for (int q = 0; q < 8; ++q) s += gs->part[q * 8 + gtid];
                ob[t * OO + gtid] = sigmoidf_(s);
            }
            if (gtid >= 40 && gtid < 40 + II && t + 1 < TT)
                gs->cat[gtid - 40] = xb[(t + 1) * II + (gtid - 40)];
            gbar(group);
        }
        gbar(group);
    }
}

extern "C" void kernel_launch(void* const* d_in, const int* in_sizes, int n_in,
                              void* d_out, int out_size) {
    const float* x      = (const float*)d_in[0];
    const float* Wc     = (const float*)d_in[1];
    const float* bc     = (const float*)d_in[2];
    const float* Wr     = (const float*)d_in[3];
    const float* br     = (const float*)d_in[4];
    const float* Ww     = (const float*)d_in[5];
    const float* bw     = (const float*)d_in[6];
    const float* Wf     = (const float*)d_in[7];
    const float* bf     = (const float*)d_in[8];
    const float* r_bias = (const float*)d_in[9];
    const float* M_bias = (const float*)d_in[10];
    float* out = (float*)d_out;

    const int Btot = in_sizes[0] / (TT * II);
    cudaFuncSetAttribute(ntm_kernel, cudaFuncAttributeMaxDynamicSharedMemorySize,
                         DYN_SMEM_BYTES);
    int grid = (Btot + NGROUPS - 1) / NGROUPS;   // 8 concurrent batches per CTA
    if (grid < 1) grid = 1;
    ntm_kernel<<<grid, 512, DYN_SMEM_BYTES>>>(x, Wc, bc, Wr, br, Ww, bw, Wf, bf,
                                              r_bias, M_bias, out, Btot);
}